// round 7
// baseline (speedup 1.0000x reference)
#include <cuda_runtime.h>

#define BATCH 8
#define HH 1024
#define WW 1024

#define TILE 104          // valid output span per tile dim
#define HALO 12           // >= 10 needed; 12 keeps alignment
#define EXT  128          // TILE + 2*HALO
#define NGROUP 16         // row groups (vertical)
#define RPW  8            // rows per group
#define NT   1024         // 32 warps: (group, half) = (w>>1, w&1)
#define NITER 10

// smem: sv0, sv1 [EXT*EXT] + xu, xq [NGROUP*EXT] + xcu, xcq [NGROUP*RPW]
#define SMEM_BYTES ((2*EXT*EXT + 2*NGROUP*EXT + 2*NGROUP*RPW) * 4)

// sigmoid(2x) = 0.5*tanh(x) + 0.5  -> one MUFU
__device__ __forceinline__ float tanh_fast(float x) {
    float y;
    asm("tanh.approx.f32 %0, %1;" : "=f"(y) : "f"(x));
    return y;
}

__global__ void __launch_bounds__(NT, 1)
ccs_fused(const float* __restrict__ o, const float* __restrict__ vf,
          float* __restrict__ out) {
    extern __shared__ float sm[];
    float* sv0 = sm;                         // vf0 [EXT][EXT] (zeroed outside image)
    float* sv1 = sm + EXT * EXT;             // vf1 [EXT][EXT]
    float* xu  = sm + 2 * EXT * EXT;         // u row-group top-row exchange [NGROUP][EXT]
    float* xq  = xu + NGROUP * EXT;          // q row-group bottom-row exchange [NGROUP][EXT]
    float* xcu = xq + NGROUP * EXT;          // u at ext col 64, per row [NGROUP][RPW]
    float* xcq = xcu + NGROUP * RPW;         // q at ext col 63, per row [NGROUP][RPW]

    const int tid  = threadIdx.x;
    const int w    = tid >> 5;
    const int lane = tid & 31;
    const int wg   = w >> 1;                 // row group 0..15
    const int h    = w & 1;                  // column half 0..1
    const int ch   = h << 6;                 // col offset within ext tile (0 or 64)
    const int er0  = wg * RPW;
    const int tx = blockIdx.x, ty = blockIdx.y, b = blockIdx.z;
    const int gi0 = ty * TILE - HALO;
    const int gj0 = tx * TILE - HALO;
    const int ec  = ch + lane * 2;           // ext col of this lane's elem 0
    const int colbase = gj0 + ec;            // global col (even)
    const int cb = min(max(colbase, 0), WW - 2);   // clamped, 8B aligned
    const float* ob = o + (size_t)b * HH * WW;

    // column in-image mask
    const float cmx = ((unsigned)(colbase + 0) < WW) ? 1.f : 0.f;
    const float cmy = ((unsigned)(colbase + 1) < WW) ? 1.f : 0.f;

    // ---- load vector field into smem, deinterleave, zero out-of-image ----
    for (int k = tid; k < EXT * EXT / 2; k += NT) {
        int er = k >> 6;              // 64 px-pairs per 128-col row
        int c2 = (k & 63) << 1;
        int gr = gi0 + er;
        int gc = gj0 + c2;
        int grc = min(max(gr, 0), HH - 1);
        int gcc = min(max(gc, 0), WW - 2);
        float4 v = *reinterpret_cast<const float4*>(vf + ((size_t)grc * WW + gcc) * 2);
        float mr = ((unsigned)gr < HH) ? 1.f : 0.f;
        float m0 = mr * (((unsigned)gc < WW) ? 1.f : 0.f);
        float m1 = mr * (((unsigned)(gc + 1) < WW) ? 1.f : 0.f);
        sv0[er * EXT + c2]     = v.x * m0;  sv1[er * EXT + c2]     = v.y * m0;
        sv0[er * EXT + c2 + 1] = v.z * m1;  sv1[er * EXT + c2 + 1] = v.w * m1;
    }

    // ---- init: u = 0.5*tanh(o)+0.5 (masked), q = 0 ----
    float2 u[RPW], q[RPW];
#pragma unroll
    for (int r = 0; r < RPW; r++) {
        int gr = gi0 + er0 + r;
        int grc = min(max(gr, 0), HH - 1);
        float2 o2 = *reinterpret_cast<const float2*>(ob + (size_t)grc * WW + cb);
        float rm = ((unsigned)gr < HH) ? 1.f : 0.f;
        u[r].x = (cmx * rm) * fmaf(tanh_fast(o2.x), 0.5f, 0.5f);
        u[r].y = (cmy * rm) * fmaf(tanh_fast(o2.y), 0.5f, 0.5f);
        q[r] = make_float2(0.f, 0.f);
    }
    *reinterpret_cast<float2*>(&xu[wg * EXT + ec]) = u[0];
    if (h == 1 && lane == 0) {
#pragma unroll
        for (int r = 0; r < RPW; r++) xcu[wg * RPW + r] = u[r].x;  // col 64
    }
    __syncthreads();

#pragma unroll 1
    for (int it = 0; it < NITER; it++) {
        const bool last = (it == NITER - 1);

        // ===== q-step: q = max(q - 0.5*((u_dn-u)*v1 + (u_rt-u)*v0), 0) =====
#pragma unroll
        for (int r = 0; r < RPW; r++) {
            int er = er0 + r;
            float2 ud;
            if (r < RPW - 1)        ud = u[r + 1];
            else if (wg < NGROUP-1) ud = *reinterpret_cast<float2*>(&xu[(wg + 1) * EXT + ec]);
            else                    ud = make_float2(0.f, 0.f);
            float ur = __shfl_down_sync(0xffffffffu, u[r].x, 1);   // col ec+2
            if (lane == 31) ur = (h == 0) ? xcu[wg * RPW + r] : 0.f;
            float2 v0 = *reinterpret_cast<float2*>(&sv0[er * EXT + ec]);
            float2 v1 = *reinterpret_cast<float2*>(&sv1[er * EXT + ec]);
            float t;
            t = (ud.x - u[r].x) * v1.x + (u[r].y - u[r].x) * v0.x;
            q[r].x = fmaxf(fmaf(-0.5f, t, q[r].x), 0.f);
            t = (ud.y - u[r].y) * v1.y + (ur - u[r].y) * v0.y;
            q[r].y = fmaxf(fmaf(-0.5f, t, q[r].y), 0.f);
        }
        *reinterpret_cast<float2*>(&xq[wg * EXT + ec]) = q[RPW - 1];
        if (h == 0 && lane == 31) {
#pragma unroll
            for (int r = 0; r < RPW; r++) xcq[wg * RPW + r] = q[r].y;  // col 63
        }
        __syncthreads();

        // ===== u-step: Tq = div(vf*q); x = o - Tq; u = 0.5*tanh(x)+0.5 (or out=2x) =====
        {
            float2 qup;
            if (wg > 0) qup = *reinterpret_cast<float2*>(&xq[(wg - 1) * EXT + ec]);
            else        qup = make_float2(0.f, 0.f);
            float2 v1p;
            if (wg > 0) v1p = *reinterpret_cast<float2*>(&sv1[(er0 - 1) * EXT + ec]);
            else        v1p = make_float2(0.f, 0.f);
#pragma unroll
            for (int r = 0; r < RPW; r++) {
                int er = er0 + r;
                int gr = gi0 + er;
                int grc = min(max(gr, 0), HH - 1);
                float2 v0 = *reinterpret_cast<float2*>(&sv0[er * EXT + ec]);
                float2 v1 = *reinterpret_cast<float2*>(&sv1[er * EXT + ec]);
                float ql  = __shfl_up_sync(0xffffffffu, q[r].y, 1);
                float v0l = __shfl_up_sync(0xffffffffu, v0.y, 1);
                if (lane == 0) {
                    if (h == 1) { ql = xcq[wg * RPW + r]; v0l = sv0[er * EXT + 63]; }
                    else        { ql = 0.f; v0l = 0.f; }
                }
                float2 o2 = *reinterpret_cast<const float2*>(ob + (size_t)grc * WW + cb);

                float Tq0 = v1.x * q[r].x - v1p.x * qup.x + v0.x * q[r].x - v0l  * ql;
                float Tq1 = v1.y * q[r].y - v1p.y * qup.y + v0.y * q[r].y - v0.x * q[r].x;
                float x0 = o2.x - Tq0;
                float x1 = o2.y - Tq1;

                if (!last) {
                    float rm = ((unsigned)gr < HH) ? 1.f : 0.f;
                    u[r].x = (cmx * rm) * fmaf(tanh_fast(x0), 0.5f, 0.5f);
                    u[r].y = (cmy * rm) * fmaf(tanh_fast(x1), 0.5f, 0.5f);
                } else {
                    // final: out = (o - Tq)/EPS = 2*x, only the tile's valid center
                    if (er >= HALO && er < HALO + TILE && gr < HH &&
                        ec >= HALO && ec < HALO + TILE && colbase < WW) {
                        *reinterpret_cast<float2*>(out + (size_t)((b * HH + gr) * WW + colbase)) =
                            make_float2(2.f * x0, 2.f * x1);
                    }
                }
                v1p = v1;
                qup = q[r];
            }
        }
        if (!last) {
            *reinterpret_cast<float2*>(&xu[wg * EXT + ec]) = u[0];
            if (h == 1 && lane == 0) {
#pragma unroll
                for (int r = 0; r < RPW; r++) xcu[wg * RPW + r] = u[r].x;
            }
        }
        __syncthreads();
    }
}

extern "C" void kernel_launch(void* const* d_in, const int* in_sizes, int n_in,
                              void* d_out, int out_size) {
    const float* o  = (const float*)d_in[0];
    const float* vf = (const float*)d_in[1];
    float* out = (float*)d_out;

    static bool attr_set = false;
    if (!attr_set) {
        cudaFuncSetAttribute(ccs_fused, cudaFuncAttributeMaxDynamicSharedMemorySize,
                             SMEM_BYTES);
        attr_set = true;
    }

    dim3 grid((WW + TILE - 1) / TILE, (HH + TILE - 1) / TILE, BATCH);  // 10 x 10 x 8
    ccs_fused<<<grid, NT, SMEM_BYTES>>>(o, vf, out);
}

// round 8
// speedup vs baseline: 1.5275x; 1.5275x over previous
#include <cuda_runtime.h>

#define BATCH 8
#define HH 1024
#define WW 1024

#define TILE 104          // valid output span per tile dim
#define HALO 12           // >= 10 needed; 12 keeps float4 alignment
#define EXT  128          // TILE + 2*HALO
#define NWARP 16
#define RPW  8            // rows per warp (NWARP*RPW == EXT)
#define NT   512
#define NITER 10

#define SMEM_BYTES ((2*EXT*EXT + 2*NWARP*EXT) * 4)

// sigmoid(2x) = 0.5*tanh(x) + 0.5  -> one MUFU
__device__ __forceinline__ float tanh_fast(float x) {
    float y;
    asm("tanh.approx.f32 %0, %1;" : "=f"(y) : "f"(x));
    return y;
}

__global__ void __launch_bounds__(NT, 1)
ccs_fused(const float* __restrict__ o, const float* __restrict__ vf,
          float* __restrict__ out) {
    extern __shared__ float sm[];
    float* sv0 = sm;                    // vf0 [EXT][EXT] (zeroed outside image)
    float* sv1 = sm + EXT * EXT;        // vf1 [EXT][EXT]
    float* xu  = sm + 2 * EXT * EXT;    // per-warp u row-0 exchange [NWARP][EXT]
    float* xq  = xu + NWARP * EXT;      // per-warp q row-7 exchange [NWARP][EXT]

    const int tid  = threadIdx.x;
    const int w    = tid >> 5;
    const int lane = tid & 31;
    const int tx = blockIdx.x, ty = blockIdx.y, b = blockIdx.z;
    const int gi0 = ty * TILE - HALO;
    const int gj0 = tx * TILE - HALO;            // multiple of 4
    const int colbase = gj0 + lane * 4;          // global col of this lane's elem 0
    const int cb = min(max(colbase, 0), WW - 4); // clamped, 16B aligned
    const int er0 = w * RPW;
    const float* ob = o + (size_t)b * HH * WW;

    // column in-image mask (constant over rows)
    float4 cm;
    cm.x = ((unsigned)(colbase + 0) < WW) ? 1.f : 0.f;
    cm.y = ((unsigned)(colbase + 1) < WW) ? 1.f : 0.f;
    cm.z = ((unsigned)(colbase + 2) < WW) ? 1.f : 0.f;
    cm.w = ((unsigned)(colbase + 3) < WW) ? 1.f : 0.f;

    // ---- load vector field into smem, deinterleave, zero out-of-image ----
    for (int k = tid; k < EXT * EXT / 2; k += NT) {
        int er = k >> 6;              // 64 px-pairs per 128-col row
        int ec = (k & 63) << 1;
        int gr = gi0 + er;
        int gc = gj0 + ec;
        int grc = min(max(gr, 0), HH - 1);
        int gcc = min(max(gc, 0), WW - 2);
        float4 v = *reinterpret_cast<const float4*>(vf + ((size_t)grc * WW + gcc) * 2);
        float mr = ((unsigned)gr < HH) ? 1.f : 0.f;
        float m0 = mr * (((unsigned)gc < WW) ? 1.f : 0.f);
        float m1 = mr * (((unsigned)(gc + 1) < WW) ? 1.f : 0.f);
        sv0[er * EXT + ec]     = v.x * m0;  sv1[er * EXT + ec]     = v.y * m0;
        sv0[er * EXT + ec + 1] = v.z * m1;  sv1[er * EXT + ec + 1] = v.w * m1;
    }

    // ---- init: u = 0.5*tanh(o)+0.5 (masked), q = 0 (register resident) ----
    float4 u[RPW], q[RPW];
#pragma unroll
    for (int r = 0; r < RPW; r++) {
        int er = er0 + r;
        int gr = gi0 + er;
        int grc = min(max(gr, 0), HH - 1);
        float4 o4 = *reinterpret_cast<const float4*>(ob + (size_t)grc * WW + cb);
        float rm = ((unsigned)gr < HH) ? 1.f : 0.f;
        u[r].x = (cm.x * rm) * fmaf(tanh_fast(o4.x), 0.5f, 0.5f);
        u[r].y = (cm.y * rm) * fmaf(tanh_fast(o4.y), 0.5f, 0.5f);
        u[r].z = (cm.z * rm) * fmaf(tanh_fast(o4.z), 0.5f, 0.5f);
        u[r].w = (cm.w * rm) * fmaf(tanh_fast(o4.w), 0.5f, 0.5f);
        q[r] = make_float4(0.f, 0.f, 0.f, 0.f);
    }
    *reinterpret_cast<float4*>(&xu[w * EXT + lane * 4]) = u[0];
    __syncthreads();

#pragma unroll 1
    for (int it = 0; it < NITER; it++) {
        const bool last = (it == NITER - 1);

        // ===== fused sweep: per row r: q_new[r]; then (r>=1) u_new[r] =====
        // q[r] = max(q[r] - 0.5*((u_dn-u)*v1 + (u_rt-u)*v0), 0)   [u = prev-iter u]
        // u[r] = sigm(2*(o - Tq[r])),  Tq uses q_new[r], q_new[r-1], vf rows r, r-1
        {
            float4 v1prev;   // v1 of row r-1 (set at end of each step)
#pragma unroll
            for (int r = 0; r < RPW; r++) {
                int er = er0 + r;
                float4 v0c = *reinterpret_cast<float4*>(&sv0[er * EXT + lane * 4]);
                float4 v1c = *reinterpret_cast<float4*>(&sv1[er * EXT + lane * 4]);

                // ---- q-update for row r (uses prev-iter u everywhere) ----
                float4 ud;
                if (r < RPW - 1)        ud = u[r + 1];
                else if (w < NWARP - 1) ud = *reinterpret_cast<float4*>(&xu[(w + 1) * EXT + lane * 4]);
                else                    ud = make_float4(0.f, 0.f, 0.f, 0.f);
                float ur = __shfl_down_sync(0xffffffffu, u[r].x, 1);
                if (lane == 31) ur = 0.f;
                float t;
                t = (ud.x - u[r].x) * v1c.x + (u[r].y - u[r].x) * v0c.x;
                q[r].x = fmaxf(fmaf(-0.5f, t, q[r].x), 0.f);
                t = (ud.y - u[r].y) * v1c.y + (u[r].z - u[r].y) * v0c.y;
                q[r].y = fmaxf(fmaf(-0.5f, t, q[r].y), 0.f);
                t = (ud.z - u[r].z) * v1c.z + (u[r].w - u[r].z) * v0c.z;
                q[r].z = fmaxf(fmaf(-0.5f, t, q[r].z), 0.f);
                t = (ud.w - u[r].w) * v1c.w + (ur - u[r].w) * v0c.w;
                q[r].w = fmaxf(fmaf(-0.5f, t, q[r].w), 0.f);

                // ---- u-update for row r (r>=1): needs q[r], q[r-1], v1prev ----
                if (r >= 1) {
                    int gr = gi0 + er;
                    int grc = min(max(gr, 0), HH - 1);
                    float ql  = __shfl_up_sync(0xffffffffu, q[r].w, 1);
                    float v0l = __shfl_up_sync(0xffffffffu, v0c.w, 1);
                    if (lane == 0) { ql = 0.f; v0l = 0.f; }
                    float4 o4 = *reinterpret_cast<const float4*>(ob + (size_t)grc * WW + cb);

                    float Tq0 = v1c.x * q[r].x - v1prev.x * q[r-1].x + v0c.x * q[r].x - v0l   * ql;
                    float Tq1 = v1c.y * q[r].y - v1prev.y * q[r-1].y + v0c.y * q[r].y - v0c.x * q[r].x;
                    float Tq2 = v1c.z * q[r].z - v1prev.z * q[r-1].z + v0c.z * q[r].z - v0c.y * q[r].y;
                    float Tq3 = v1c.w * q[r].w - v1prev.w * q[r-1].w + v0c.w * q[r].w - v0c.z * q[r].z;
                    float x0 = o4.x - Tq0;
                    float x1 = o4.y - Tq1;
                    float x2 = o4.z - Tq2;
                    float x3 = o4.w - Tq3;

                    if (!last) {
                        float rm = ((unsigned)gr < HH) ? 1.f : 0.f;
                        u[r].x = (cm.x * rm) * fmaf(tanh_fast(x0), 0.5f, 0.5f);
                        u[r].y = (cm.y * rm) * fmaf(tanh_fast(x1), 0.5f, 0.5f);
                        u[r].z = (cm.z * rm) * fmaf(tanh_fast(x2), 0.5f, 0.5f);
                        u[r].w = (cm.w * rm) * fmaf(tanh_fast(x3), 0.5f, 0.5f);
                    } else {
                        if (er >= HALO && er < HALO + TILE && gr < HH &&
                            lane >= HALO / 4 && lane < (HALO + TILE) / 4 && colbase < WW) {
                            *reinterpret_cast<float4*>(out + (size_t)((b * HH + gr) * WW + colbase)) =
                                make_float4(2.f * x0, 2.f * x1, 2.f * x2, 2.f * x3);
                        }
                    }
                }
                v1prev = v1c;
            }
        }
        *reinterpret_cast<float4*>(&xq[w * EXT + lane * 4]) = q[RPW - 1];
        __syncthreads();

        // ===== epilogue: u-update for row 0 (needs q[7] of warp above via xq) =====
        {
            int er = er0;
            int gr = gi0 + er;
            int grc = min(max(gr, 0), HH - 1);
            float4 qup, v1p;
            if (w > 0) {
                qup = *reinterpret_cast<float4*>(&xq[(w - 1) * EXT + lane * 4]);
                v1p = *reinterpret_cast<float4*>(&sv1[(er0 - 1) * EXT + lane * 4]);
            } else {
                qup = make_float4(0.f, 0.f, 0.f, 0.f);
                v1p = make_float4(0.f, 0.f, 0.f, 0.f);
            }
            float4 v00 = *reinterpret_cast<float4*>(&sv0[er * EXT + lane * 4]);
            float4 v10 = *reinterpret_cast<float4*>(&sv1[er * EXT + lane * 4]);
            float ql  = __shfl_up_sync(0xffffffffu, q[0].w, 1);
            float v0l = __shfl_up_sync(0xffffffffu, v00.w, 1);
            if (lane == 0) { ql = 0.f; v0l = 0.f; }
            float4 o4 = *reinterpret_cast<const float4*>(ob + (size_t)grc * WW + cb);

            float Tq0 = v10.x * q[0].x - v1p.x * qup.x + v00.x * q[0].x - v0l   * ql;
            float Tq1 = v10.y * q[0].y - v1p.y * qup.y + v00.y * q[0].y - v00.x * q[0].x;
            float Tq2 = v10.z * q[0].z - v1p.z * qup.z + v00.z * q[0].z - v00.y * q[0].y;
            float Tq3 = v10.w * q[0].w - v1p.w * qup.w + v00.w * q[0].w - v00.z * q[0].z;
            float x0 = o4.x - Tq0;
            float x1 = o4.y - Tq1;
            float x2 = o4.z - Tq2;
            float x3 = o4.w - Tq3;

            if (!last) {
                float rm = ((unsigned)gr < HH) ? 1.f : 0.f;
                u[0].x = (cm.x * rm) * fmaf(tanh_fast(x0), 0.5f, 0.5f);
                u[0].y = (cm.y * rm) * fmaf(tanh_fast(x1), 0.5f, 0.5f);
                u[0].z = (cm.z * rm) * fmaf(tanh_fast(x2), 0.5f, 0.5f);
                u[0].w = (cm.w * rm) * fmaf(tanh_fast(x3), 0.5f, 0.5f);
                *reinterpret_cast<float4*>(&xu[w * EXT + lane * 4]) = u[0];
            } else {
                if (er >= HALO && er < HALO + TILE && gr < HH &&
                    lane >= HALO / 4 && lane < (HALO + TILE) / 4 && colbase < WW) {
                    *reinterpret_cast<float4*>(out + (size_t)((b * HH + gr) * WW + colbase)) =
                        make_float4(2.f * x0, 2.f * x1, 2.f * x2, 2.f * x3);
                }
            }
        }
        if (!last) __syncthreads();
    }
}

extern "C" void kernel_launch(void* const* d_in, const int* in_sizes, int n_in,
                              void* d_out, int out_size) {
    const float* o  = (const float*)d_in[0];
    const float* vf = (const float*)d_in[1];
    float* out = (float*)d_out;

    static bool attr_set = false;
    if (!attr_set) {
        cudaFuncSetAttribute(ccs_fused, cudaFuncAttributeMaxDynamicSharedMemorySize,
                             SMEM_BYTES);
        attr_set = true;
    }

    dim3 grid((WW + TILE - 1) / TILE, (HH + TILE - 1) / TILE, BATCH);  // 10 x 10 x 8
    ccs_fused<<<grid, NT, SMEM_BYTES>>>(o, vf, out);
}

// round 9
// speedup vs baseline: 1.7042x; 1.1157x over previous
#include <cuda_runtime.h>

#define BATCH 8
#define HH 1024
#define WW 1024

#define TILE 104          // valid output span per tile dim
#define HALO 12           // >= 10 needed; 12 keeps float4 alignment
#define EXT  128          // TILE + 2*HALO
#define NWARP 16
#define RPW  8            // rows per warp (NWARP*RPW == EXT)
#define NT   512
#define NITER 10

#define SMEM_BYTES ((2*EXT*EXT + 2*NWARP*EXT) * 4)

// sigmoid(2x) = 0.5*tanh(x) + 0.5  -> one MUFU
__device__ __forceinline__ float tanh_fast(float x) {
    float y;
    asm("tanh.approx.f32 %0, %1;" : "=f"(y) : "f"(x));
    return y;
}

template <bool INTERIOR>
__device__ __forceinline__ void run_tile(
    const float* __restrict__ o, const float* __restrict__ vf,
    float* __restrict__ out, float* sm, int tx, int ty, int b)
{
    float* sv0 = sm;                    // vf0 [EXT][EXT] (zeroed outside image)
    float* sv1 = sm + EXT * EXT;        // vf1 [EXT][EXT]
    float* xu  = sm + 2 * EXT * EXT;    // per-warp u row-0 exchange [NWARP][EXT]
    float* xq  = xu + NWARP * EXT;      // per-warp q row-7 exchange [NWARP][EXT]

    const int tid  = threadIdx.x;
    const int w    = tid >> 5;
    const int lane = tid & 31;
    const int gi0 = ty * TILE - HALO;
    const int gj0 = tx * TILE - HALO;            // multiple of 4
    const int colbase = gj0 + lane * 4;          // global col of this lane's elem 0
    const int cb = INTERIOR ? colbase : min(max(colbase, 0), WW - 4); // 16B aligned
    const int er0 = w * RPW;
    const float* ob = o + (size_t)b * HH * WW;

    // column in-image mask (boundary tiles only)
    float4 cm;
    if (!INTERIOR) {
        cm.x = ((unsigned)(colbase + 0) < WW) ? 1.f : 0.f;
        cm.y = ((unsigned)(colbase + 1) < WW) ? 1.f : 0.f;
        cm.z = ((unsigned)(colbase + 2) < WW) ? 1.f : 0.f;
        cm.w = ((unsigned)(colbase + 3) < WW) ? 1.f : 0.f;
    }

    // ---- load vector field into smem, deinterleave (zero out-of-image) ----
    for (int k = tid; k < EXT * EXT / 2; k += NT) {
        int er = k >> 6;              // 64 px-pairs per 128-col row
        int ec = (k & 63) << 1;
        int gr = gi0 + er;
        int gc = gj0 + ec;
        if (INTERIOR) {
            float4 v = *reinterpret_cast<const float4*>(vf + ((size_t)gr * WW + gc) * 2);
            sv0[er * EXT + ec]     = v.x;  sv1[er * EXT + ec]     = v.y;
            sv0[er * EXT + ec + 1] = v.z;  sv1[er * EXT + ec + 1] = v.w;
        } else {
            int grc = min(max(gr, 0), HH - 1);
            int gcc = min(max(gc, 0), WW - 2);
            float4 v = *reinterpret_cast<const float4*>(vf + ((size_t)grc * WW + gcc) * 2);
            float mr = ((unsigned)gr < HH) ? 1.f : 0.f;
            float m0 = mr * (((unsigned)gc < WW) ? 1.f : 0.f);
            float m1 = mr * (((unsigned)(gc + 1) < WW) ? 1.f : 0.f);
            sv0[er * EXT + ec]     = v.x * m0;  sv1[er * EXT + ec]     = v.y * m0;
            sv0[er * EXT + ec + 1] = v.z * m1;  sv1[er * EXT + ec + 1] = v.w * m1;
        }
    }

    // ---- init: u = 0.5*tanh(o)+0.5 (masked on boundary), q = 0 ----
    float4 u[RPW], q[RPW];
#pragma unroll
    for (int r = 0; r < RPW; r++) {
        int er = er0 + r;
        int gr = gi0 + er;
        int grc = INTERIOR ? gr : min(max(gr, 0), HH - 1);
        float4 o4 = *reinterpret_cast<const float4*>(ob + (size_t)grc * WW + cb);
        if (INTERIOR) {
            u[r].x = fmaf(tanh_fast(o4.x), 0.5f, 0.5f);
            u[r].y = fmaf(tanh_fast(o4.y), 0.5f, 0.5f);
            u[r].z = fmaf(tanh_fast(o4.z), 0.5f, 0.5f);
            u[r].w = fmaf(tanh_fast(o4.w), 0.5f, 0.5f);
        } else {
            float rm = ((unsigned)gr < HH) ? 1.f : 0.f;
            u[r].x = (cm.x * rm) * fmaf(tanh_fast(o4.x), 0.5f, 0.5f);
            u[r].y = (cm.y * rm) * fmaf(tanh_fast(o4.y), 0.5f, 0.5f);
            u[r].z = (cm.z * rm) * fmaf(tanh_fast(o4.z), 0.5f, 0.5f);
            u[r].w = (cm.w * rm) * fmaf(tanh_fast(o4.w), 0.5f, 0.5f);
        }
        q[r] = make_float4(0.f, 0.f, 0.f, 0.f);
    }
    *reinterpret_cast<float4*>(&xu[w * EXT + lane * 4]) = u[0];
    __syncthreads();

#pragma unroll 1
    for (int it = 0; it < NITER; it++) {
        const bool last = (it == NITER - 1);

        // ===== fused sweep: per row r: q_new[r]; then (r>=1) u_new[r] =====
        {
            float4 v1prev;
#pragma unroll
            for (int r = 0; r < RPW; r++) {
                int er = er0 + r;
                float4 v0c = *reinterpret_cast<float4*>(&sv0[er * EXT + lane * 4]);
                float4 v1c = *reinterpret_cast<float4*>(&sv1[er * EXT + lane * 4]);

                // ---- q-update row r (prev-iter u) ----
                float4 ud;
                if (r < RPW - 1)        ud = u[r + 1];
                else if (w < NWARP - 1) ud = *reinterpret_cast<float4*>(&xu[(w + 1) * EXT + lane * 4]);
                else                    ud = make_float4(0.f, 0.f, 0.f, 0.f);
                float ur = __shfl_down_sync(0xffffffffu, u[r].x, 1);
                if (lane == 31) ur = 0.f;
                float t;
                t = (ud.x - u[r].x) * v1c.x + (u[r].y - u[r].x) * v0c.x;
                q[r].x = fmaxf(fmaf(-0.5f, t, q[r].x), 0.f);
                t = (ud.y - u[r].y) * v1c.y + (u[r].z - u[r].y) * v0c.y;
                q[r].y = fmaxf(fmaf(-0.5f, t, q[r].y), 0.f);
                t = (ud.z - u[r].z) * v1c.z + (u[r].w - u[r].z) * v0c.z;
                q[r].z = fmaxf(fmaf(-0.5f, t, q[r].z), 0.f);
                t = (ud.w - u[r].w) * v1c.w + (ur - u[r].w) * v0c.w;
                q[r].w = fmaxf(fmaf(-0.5f, t, q[r].w), 0.f);

                // ---- u-update row r (r>=1): p = v0 ⊙ q, single shfl of p.w ----
                if (r >= 1) {
                    int gr = gi0 + er;
                    int grc = INTERIOR ? gr : min(max(gr, 0), HH - 1);
                    float4 p;
                    p.x = v0c.x * q[r].x;
                    p.y = v0c.y * q[r].y;
                    p.z = v0c.z * q[r].z;
                    p.w = v0c.w * q[r].w;
                    float pl = __shfl_up_sync(0xffffffffu, p.w, 1);
                    if (lane == 0) pl = 0.f;
                    float4 o4 = *reinterpret_cast<const float4*>(ob + (size_t)grc * WW + cb);

                    float Tq0 = v1c.x * q[r].x - v1prev.x * q[r-1].x + p.x - pl;
                    float Tq1 = v1c.y * q[r].y - v1prev.y * q[r-1].y + p.y - p.x;
                    float Tq2 = v1c.z * q[r].z - v1prev.z * q[r-1].z + p.z - p.y;
                    float Tq3 = v1c.w * q[r].w - v1prev.w * q[r-1].w + p.w - p.z;
                    float x0 = o4.x - Tq0;
                    float x1 = o4.y - Tq1;
                    float x2 = o4.z - Tq2;
                    float x3 = o4.w - Tq3;

                    if (!last) {
                        if (INTERIOR) {
                            u[r].x = fmaf(tanh_fast(x0), 0.5f, 0.5f);
                            u[r].y = fmaf(tanh_fast(x1), 0.5f, 0.5f);
                            u[r].z = fmaf(tanh_fast(x2), 0.5f, 0.5f);
                            u[r].w = fmaf(tanh_fast(x3), 0.5f, 0.5f);
                        } else {
                            float rm = ((unsigned)gr < HH) ? 1.f : 0.f;
                            u[r].x = (cm.x * rm) * fmaf(tanh_fast(x0), 0.5f, 0.5f);
                            u[r].y = (cm.y * rm) * fmaf(tanh_fast(x1), 0.5f, 0.5f);
                            u[r].z = (cm.z * rm) * fmaf(tanh_fast(x2), 0.5f, 0.5f);
                            u[r].w = (cm.w * rm) * fmaf(tanh_fast(x3), 0.5f, 0.5f);
                        }
                    } else {
                        bool ok = (er >= HALO && er < HALO + TILE &&
                                   lane >= HALO / 4 && lane < (HALO + TILE) / 4);
                        if (!INTERIOR) ok = ok && gr < HH && colbase < WW;
                        if (ok) {
                            *reinterpret_cast<float4*>(out + (size_t)((b * HH + gr) * WW + colbase)) =
                                make_float4(2.f * x0, 2.f * x1, 2.f * x2, 2.f * x3);
                        }
                    }
                }
                v1prev = v1c;
            }
        }
        *reinterpret_cast<float4*>(&xq[w * EXT + lane * 4]) = q[RPW - 1];
        __syncthreads();

        // ===== epilogue: u-update row 0 (needs q[7] of warp above) =====
        {
            int er = er0;
            int gr = gi0 + er;
            int grc = INTERIOR ? gr : min(max(gr, 0), HH - 1);
            float4 qup, v1p;
            if (w > 0) {
                qup = *reinterpret_cast<float4*>(&xq[(w - 1) * EXT + lane * 4]);
                v1p = *reinterpret_cast<float4*>(&sv1[(er0 - 1) * EXT + lane * 4]);
            } else {
                qup = make_float4(0.f, 0.f, 0.f, 0.f);
                v1p = make_float4(0.f, 0.f, 0.f, 0.f);
            }
            float4 v00 = *reinterpret_cast<float4*>(&sv0[er * EXT + lane * 4]);
            float4 v10 = *reinterpret_cast<float4*>(&sv1[er * EXT + lane * 4]);
            float4 p;
            p.x = v00.x * q[0].x;
            p.y = v00.y * q[0].y;
            p.z = v00.z * q[0].z;
            p.w = v00.w * q[0].w;
            float pl = __shfl_up_sync(0xffffffffu, p.w, 1);
            if (lane == 0) pl = 0.f;
            float4 o4 = *reinterpret_cast<const float4*>(ob + (size_t)grc * WW + cb);

            float Tq0 = v10.x * q[0].x - v1p.x * qup.x + p.x - pl;
            float Tq1 = v10.y * q[0].y - v1p.y * qup.y + p.y - p.x;
            float Tq2 = v10.z * q[0].z - v1p.z * qup.z + p.z - p.y;
            float Tq3 = v10.w * q[0].w - v1p.w * qup.w + p.w - p.z;
            float x0 = o4.x - Tq0;
            float x1 = o4.y - Tq1;
            float x2 = o4.z - Tq2;
            float x3 = o4.w - Tq3;

            if (!last) {
                if (INTERIOR) {
                    u[0].x = fmaf(tanh_fast(x0), 0.5f, 0.5f);
                    u[0].y = fmaf(tanh_fast(x1), 0.5f, 0.5f);
                    u[0].z = fmaf(tanh_fast(x2), 0.5f, 0.5f);
                    u[0].w = fmaf(tanh_fast(x3), 0.5f, 0.5f);
                } else {
                    float rm = ((unsigned)gr < HH) ? 1.f : 0.f;
                    u[0].x = (cm.x * rm) * fmaf(tanh_fast(x0), 0.5f, 0.5f);
                    u[0].y = (cm.y * rm) * fmaf(tanh_fast(x1), 0.5f, 0.5f);
                    u[0].z = (cm.z * rm) * fmaf(tanh_fast(x2), 0.5f, 0.5f);
                    u[0].w = (cm.w * rm) * fmaf(tanh_fast(x3), 0.5f, 0.5f);
                }
                *reinterpret_cast<float4*>(&xu[w * EXT + lane * 4]) = u[0];
            } else {
                bool ok = (er >= HALO && er < HALO + TILE &&
                           lane >= HALO / 4 && lane < (HALO + TILE) / 4);
                if (!INTERIOR) ok = ok && gr < HH && colbase < WW;
                if (ok) {
                    *reinterpret_cast<float4*>(out + (size_t)((b * HH + gr) * WW + colbase)) =
                        make_float4(2.f * x0, 2.f * x1, 2.f * x2, 2.f * x3);
                }
            }
        }
        if (!last) __syncthreads();
    }
}

__global__ void __launch_bounds__(NT, 1)
ccs_fused(const float* __restrict__ o, const float* __restrict__ vf,
          float* __restrict__ out) {
    extern __shared__ float sm[];
    const int tx = blockIdx.x, ty = blockIdx.y, b = blockIdx.z;
    // interior tile: its EXT window never leaves the image
    const bool interior = (tx >= 1) && (tx <= 8) && (ty >= 1) && (ty <= 8);
    if (interior) run_tile<true >(o, vf, out, sm, tx, ty, b);
    else          run_tile<false>(o, vf, out, sm, tx, ty, b);
}

extern "C" void kernel_launch(void* const* d_in, const int* in_sizes, int n_in,
                              void* d_out, int out_size) {
    const float* o  = (const float*)d_in[0];
    const float* vf = (const float*)d_in[1];
    float* out = (float*)d_out;

    static bool attr_set = false;
    if (!attr_set) {
        cudaFuncSetAttribute(ccs_fused, cudaFuncAttributeMaxDynamicSharedMemorySize,
                             SMEM_BYTES);
        attr_set = true;
    }

    dim3 grid((WW + TILE - 1) / TILE, (HH + TILE - 1) / TILE, BATCH);  // 10 x 10 x 8
    ccs_fused<<<grid, NT, SMEM_BYTES>>>(o, vf, out);
}